// round 1
// baseline (speedup 1.0000x reference)
#include <cuda_runtime.h>
#include <stdint.h>

#define NCAND 1600
#define NITER 100
#define NZ    16
#define TILE  4096
#define CBLK  320
#define KPT   5          // CBLK * KPT == NCAND
#define MAXTILES 1024

// ---------------- device scratch (no allocations allowed) ----------------
__device__ unsigned g_min_enc;
__device__ unsigned g_max_enc;
__device__ float4   g_cand[NCAND];     // (inv_s, s, lo=-zp, hi=15-zp)
__device__ float    g_newmin[NCAND];
__device__ float    g_newmax[NCAND];
__device__ float    g_partial[MAXTILES * NCAND];
__device__ double   g_score[NCAND];

// monotonic float<->uint encoding so unsigned atomicMin/Max order floats
__device__ __forceinline__ unsigned enc_f(float f) {
    unsigned u = __float_as_uint(f);
    return (u & 0x80000000u) ? ~u : (u | 0x80000000u);
}
__device__ __forceinline__ float dec_f(unsigned e) {
    return (e & 0x80000000u) ? __uint_as_float(e & 0x7fffffffu)
                             : __uint_as_float(~e);
}

__global__ void init_kernel() {
    g_min_enc = 0xFFFFFFFFu;
    g_max_enc = 0u;
}

// ---------------- pass A: global min/max ----------------
__global__ void minmax_kernel(const float4* __restrict__ x4, int n4) {
    float lmin = 3.4e38f, lmax = -3.4e38f;
    for (int i = blockIdx.x * blockDim.x + threadIdx.x; i < n4;
         i += gridDim.x * blockDim.x) {
        float4 v = x4[i];
        lmin = fminf(lmin, fminf(fminf(v.x, v.y), fminf(v.z, v.w)));
        lmax = fmaxf(lmax, fmaxf(fmaxf(v.x, v.y), fmaxf(v.z, v.w)));
    }
    #pragma unroll
    for (int o = 16; o; o >>= 1) {
        lmin = fminf(lmin, __shfl_xor_sync(0xffffffffu, lmin, o));
        lmax = fmaxf(lmax, __shfl_xor_sync(0xffffffffu, lmax, o));
    }
    __shared__ float smin[8], smax[8];
    int w = threadIdx.x >> 5;
    if ((threadIdx.x & 31) == 0) { smin[w] = lmin; smax[w] = lmax; }
    __syncthreads();
    if (threadIdx.x == 0) {
        int nw = blockDim.x >> 5;
        for (int i = 1; i < nw; i++) {
            lmin = fminf(lmin, smin[i]);
            lmax = fmaxf(lmax, smax[i]);
        }
        atomicMin(&g_min_enc, enc_f(lmin));
        atomicMax(&g_max_enc, enc_f(lmax));
    }
}

// ---------------- pass B: 1600 candidate params ----------------
__global__ void cand_kernel() {
    const float x_min = dec_f(g_min_enc);
    const float x_max = dec_f(g_max_enc);
    const float xrange = x_max - x_min;
    const float EPS = 1.1920929e-7f;  // np.finfo(float32).eps
    for (int c = threadIdx.x; c < NCAND; c += blockDim.x) {
        int i = c / NZ + 1;   // 1..100
        int z = c % NZ;       // 0..15
        float fi = (float)i, fz = (float)z;
        float tmp_max   = xrange / 100.0f * fi;
        float tmp_delta = tmp_max / 15.0f;
        float new_min = fmaxf(-fz * tmp_delta, x_min);
        float new_max = fminf(tmp_max - fz * tmp_delta, x_max);
        float min_neg = fminf(new_min, 0.0f);
        float max_pos = fmaxf(new_max, 0.0f);
        float scale = fmaxf((max_pos - min_neg) / 15.0f, EPS);
        // jnp.round == rint (half-to-even)
        float zp = fminf(fmaxf(0.0f - rintf(min_neg / scale), 0.0f), 15.0f);
        float inv_s = 1.0f / scale;
        g_cand[c] = make_float4(inv_s, scale, -zp, 15.0f - zp);
        g_newmin[c] = new_min;
        g_newmax[c] = new_max;
    }
}

// one quantize-MSE eval: 4 fma-pipe + 2 alu-pipe ops
__device__ __forceinline__ void eval1(float xx, const float4& p, float& acc) {
    const float MAGIC = 12582912.0f;  // 1.5 * 2^23 : round-to-nearest-even
    float t = fmaf(xx, p.x, MAGIC);
    float r = t - MAGIC;                       // = rint(x * inv_s) where it matters
    float q = fminf(fmaxf(r, p.z), p.w);       // clamp to [-zp, 15-zp]
    float d = fmaf(q, p.y, -xx);               // xq - x
    acc = fmaf(d, d, acc);
}

// ---------------- pass C: the 6.7G-eval score kernel ----------------
__global__ void __launch_bounds__(CBLK) score_kernel(const float* __restrict__ x) {
    __shared__ float sh[TILE];
    const int b = blockIdx.x;
    const float* xp = x + (size_t)b * TILE;
    for (int i = threadIdx.x; i < TILE; i += CBLK) sh[i] = xp[i];

    float4 p[KPT];
    float  acc[KPT];
    #pragma unroll
    for (int k = 0; k < KPT; k++) {
        p[k] = g_cand[threadIdx.x + k * CBLK];
        acc[k] = 0.0f;
    }
    __syncthreads();

    const float4* s4 = (const float4*)sh;
    #pragma unroll 2
    for (int e = 0; e < TILE / 4; e++) {
        float4 xv = s4[e];   // broadcast across warp (all lanes same addr)
        #pragma unroll
        for (int k = 0; k < KPT; k++) {
            eval1(xv.x, p[k], acc[k]);
            eval1(xv.y, p[k], acc[k]);
            eval1(xv.z, p[k], acc[k]);
            eval1(xv.w, p[k], acc[k]);
        }
    }

    #pragma unroll
    for (int k = 0; k < KPT; k++)
        g_partial[b * NCAND + threadIdx.x + k * CBLK] = acc[k];
}

// ---------------- pass D: deterministic fixed-order reduction ----------------
__global__ void reduce_kernel(int ntiles) {
    int c = blockIdx.x * blockDim.x + threadIdx.x;
    if (c >= NCAND) return;
    double s = 0.0;
    for (int b = 0; b < ntiles; b++)
        s += (double)g_partial[b * NCAND + c];
    g_score[c] = s;
}

// ---------------- pass E: replicate the reference scan exactly ----------------
__global__ void select_kernel(float* __restrict__ out) {
    double best = 1e30;
    float bmin = dec_f(g_min_enc);
    float bmax = dec_f(g_max_enc);
    for (int i = 0; i < NITER; i++) {
        int j = 0;
        double sm = g_score[i * NZ];
        for (int z = 1; z < NZ; z++) {        // first-occurrence argmin
            double s = g_score[i * NZ + z];
            if (s < sm) { sm = s; j = z; }
        }
        if (sm < best) {                       // strict <, like reference
            best = sm;
            bmin = g_newmin[i * NZ + j];
            bmax = g_newmax[i * NZ + j];
        }
    }
    out[0] = bmin;
    out[1] = bmax;
}

extern "C" void kernel_launch(void* const* d_in, const int* in_sizes, int n_in,
                              void* d_out, int out_size) {
    const float* x = (const float*)d_in[0];
    int n = in_sizes[0];
    int ntiles = n / TILE;           // 1024 for 1024x4096
    if (ntiles > MAXTILES) ntiles = MAXTILES;

    init_kernel<<<1, 1>>>();
    minmax_kernel<<<512, 256>>>((const float4*)x, n / 4);
    cand_kernel<<<1, 256>>>();
    score_kernel<<<ntiles, CBLK>>>(x);
    reduce_kernel<<<(NCAND + 255) / 256, 256>>>(ntiles);
    select_kernel<<<1, 1>>>((float*)d_out);
}

// round 2
// speedup vs baseline: 1.0185x; 1.0185x over previous
#include <cuda_runtime.h>
#include <stdint.h>

#define NCAND 1600
#define NITER 100
#define NZ    16
#define TILE  4096
#define CBLK  320
#define KPT   5          // CBLK * KPT == NCAND
#define MAXTILES 1024

typedef unsigned long long u64;

// ---------------- device scratch (no allocations allowed) ----------------
__device__ unsigned g_min_enc;
__device__ unsigned g_max_enc;
__device__ u64      g_invs2[NCAND];    // packed (inv_s, inv_s)
__device__ u64      g_negs2[NCAND];    // packed (-s, -s)
__device__ float    g_lo[NCAND];       // -zp
__device__ float    g_hi[NCAND];       // 15 - zp
__device__ float    g_newmin[NCAND];
__device__ float    g_newmax[NCAND];
__device__ float    g_partial[MAXTILES * NCAND];
__device__ double   g_score[NCAND];

// monotonic float<->uint encoding so unsigned atomicMin/Max order floats
__device__ __forceinline__ unsigned enc_f(float f) {
    unsigned u = __float_as_uint(f);
    return (u & 0x80000000u) ? ~u : (u | 0x80000000u);
}
__device__ __forceinline__ float dec_f(unsigned e) {
    return (e & 0x80000000u) ? __uint_as_float(e & 0x7fffffffu)
                             : __uint_as_float(~e);
}

__device__ __forceinline__ u64 pack2(float a, float b) {
    u64 r;
    asm("mov.b64 %0, {%1, %2};" : "=l"(r) : "f"(a), "f"(b));
    return r;
}

__global__ void init_kernel() {
    g_min_enc = 0xFFFFFFFFu;
    g_max_enc = 0u;
}

// ---------------- pass A: global min/max ----------------
__global__ void minmax_kernel(const float4* __restrict__ x4, int n4) {
    float lmin = 3.4e38f, lmax = -3.4e38f;
    for (int i = blockIdx.x * blockDim.x + threadIdx.x; i < n4;
         i += gridDim.x * blockDim.x) {
        float4 v = x4[i];
        lmin = fminf(lmin, fminf(fminf(v.x, v.y), fminf(v.z, v.w)));
        lmax = fmaxf(lmax, fmaxf(fmaxf(v.x, v.y), fmaxf(v.z, v.w)));
    }
    #pragma unroll
    for (int o = 16; o; o >>= 1) {
        lmin = fminf(lmin, __shfl_xor_sync(0xffffffffu, lmin, o));
        lmax = fmaxf(lmax, __shfl_xor_sync(0xffffffffu, lmax, o));
    }
    __shared__ float smin[8], smax[8];
    int w = threadIdx.x >> 5;
    if ((threadIdx.x & 31) == 0) { smin[w] = lmin; smax[w] = lmax; }
    __syncthreads();
    if (threadIdx.x == 0) {
        int nw = blockDim.x >> 5;
        for (int i = 1; i < nw; i++) {
            lmin = fminf(lmin, smin[i]);
            lmax = fmaxf(lmax, smax[i]);
        }
        atomicMin(&g_min_enc, enc_f(lmin));
        atomicMax(&g_max_enc, enc_f(lmax));
    }
}

// ---------------- pass B: 1600 candidate params ----------------
__global__ void cand_kernel() {
    const float x_min = dec_f(g_min_enc);
    const float x_max = dec_f(g_max_enc);
    const float xrange = x_max - x_min;
    const float EPS = 1.1920929e-7f;  // np.finfo(float32).eps
    for (int c = threadIdx.x; c < NCAND; c += blockDim.x) {
        int i = c / NZ + 1;   // 1..100
        int z = c % NZ;       // 0..15
        float fi = (float)i, fz = (float)z;
        float tmp_max   = xrange / 100.0f * fi;
        float tmp_delta = tmp_max / 15.0f;
        float new_min = fmaxf(-fz * tmp_delta, x_min);
        float new_max = fminf(tmp_max - fz * tmp_delta, x_max);
        float min_neg = fminf(new_min, 0.0f);
        float max_pos = fmaxf(new_max, 0.0f);
        float scale = fmaxf((max_pos - min_neg) / 15.0f, EPS);
        // jnp.round == rint (half-to-even)
        float zp = fminf(fmaxf(0.0f - rintf(min_neg / scale), 0.0f), 15.0f);
        float inv_s = 1.0f / scale;
        g_invs2[c] = pack2(inv_s, inv_s);
        g_negs2[c] = pack2(-scale, -scale);
        g_lo[c] = -zp;
        g_hi[c] = 15.0f - zp;
        g_newmin[c] = new_min;
        g_newmax[c] = new_max;
    }
}

// one packed quantize-MSE eval of 2 elements:
//   4 f32x2 fma-pipe ops + 4 scalar FMNMX (alu pipe)
// MAGIC = 12582912.0f (1.5*2^23): fma(x,inv,MAGIC)-MAGIC == rint(x*inv)
// for |x*inv| < 2^22 (guaranteed: |x*inv| <= ~1500 here).
__device__ __forceinline__ void eval2(u64 x2, u64 invs2, u64 negs2,
                                      float lo, float hi, u64& acc2) {
    const u64 MAGIC2    = 0x4B4000004B400000ull;  // (12582912, 12582912)
    const u64 NEGMAGIC2 = 0xCB400000CB400000ull;
    asm("{\n\t"
        ".reg .b64 t2, r2, q2, d2;\n\t"
        ".reg .f32 r0, r1;\n\t"
        "fma.rn.f32x2 t2, %1, %2, %5;\n\t"   // t = x*inv_s + MAGIC
        "add.rn.f32x2 r2, t2, %6;\n\t"       // r = t - MAGIC = rint(x*inv_s)
        "mov.b64 {r0, r1}, r2;\n\t"
        "max.f32 r0, r0, %3;\n\t"
        "min.f32 r0, r0, %4;\n\t"
        "max.f32 r1, r1, %3;\n\t"
        "min.f32 r1, r1, %4;\n\t"
        "mov.b64 q2, {r0, r1};\n\t"
        "fma.rn.f32x2 d2, q2, %7, %1;\n\t"   // d = x - q*s  (exact neg of q*s-x)
        "fma.rn.f32x2 %0, d2, d2, %0;\n\t"   // acc += d*d
        "}"
        : "+l"(acc2)
        : "l"(x2), "l"(invs2), "f"(lo), "f"(hi),
          "l"(MAGIC2), "l"(NEGMAGIC2), "l"(negs2));
}

// ---------------- pass C: the 6.7G-eval score kernel ----------------
__global__ void __launch_bounds__(CBLK) score_kernel(const float* __restrict__ x) {
    __shared__ float sh[TILE];
    const int b = blockIdx.x;
    const float* xp = x + (size_t)b * TILE;
    for (int i = threadIdx.x; i < TILE; i += CBLK) sh[i] = xp[i];

    u64 invs[KPT], negs[KPT], acc[KPT];
    float lo[KPT], hi[KPT];
    #pragma unroll
    for (int k = 0; k < KPT; k++) {
        int c = threadIdx.x + k * CBLK;
        invs[k] = g_invs2[c];
        negs[k] = g_negs2[c];
        lo[k]   = g_lo[c];
        hi[k]   = g_hi[c];
        acc[k]  = 0ull;      // packed (0.0f, 0.0f)
    }
    __syncthreads();

    const ulonglong2* s2 = (const ulonglong2*)sh;   // 2 packed pairs per 128b
    #pragma unroll 2
    for (int e = 0; e < TILE / 4; e++) {
        ulonglong2 xv = s2[e];   // broadcast LDS.128 (all lanes same addr)
        #pragma unroll
        for (int k = 0; k < KPT; k++) {
            eval2(xv.x, invs[k], negs[k], lo[k], hi[k], acc[k]);
            eval2(xv.y, invs[k], negs[k], lo[k], hi[k], acc[k]);
        }
    }

    #pragma unroll
    for (int k = 0; k < KPT; k++) {
        float a0, a1;
        asm("mov.b64 {%0, %1}, %2;" : "=f"(a0), "=f"(a1) : "l"(acc[k]));
        g_partial[b * NCAND + threadIdx.x + k * CBLK] = a0 + a1;
    }
}

// ---------------- pass D: deterministic fixed-order reduction ----------------
__global__ void reduce_kernel(int ntiles) {
    int c = blockIdx.x * blockDim.x + threadIdx.x;
    if (c >= NCAND) return;
    double s = 0.0;
    for (int b = 0; b < ntiles; b++)
        s += (double)g_partial[b * NCAND + c];
    g_score[c] = s;
}

// ---------------- pass E: replicate the reference scan exactly ----------------
__global__ void select_kernel(float* __restrict__ out) {
    double best = 1e30;
    float bmin = dec_f(g_min_enc);
    float bmax = dec_f(g_max_enc);
    for (int i = 0; i < NITER; i++) {
        int j = 0;
        double sm = g_score[i * NZ];
        for (int z = 1; z < NZ; z++) {        // first-occurrence argmin
            double s = g_score[i * NZ + z];
            if (s < sm) { sm = s; j = z; }
        }
        if (sm < best) {                       // strict <, like reference
            best = sm;
            bmin = g_newmin[i * NZ + j];
            bmax = g_newmax[i * NZ + j];
        }
    }
    out[0] = bmin;
    out[1] = bmax;
}

extern "C" void kernel_launch(void* const* d_in, const int* in_sizes, int n_in,
                              void* d_out, int out_size) {
    const float* x = (const float*)d_in[0];
    int n = in_sizes[0];
    int ntiles = n / TILE;           // 1024 for 1024x4096
    if (ntiles > MAXTILES) ntiles = MAXTILES;

    init_kernel<<<1, 1>>>();
    minmax_kernel<<<512, 256>>>((const float4*)x, n / 4);
    cand_kernel<<<1, 256>>>();
    score_kernel<<<ntiles, CBLK>>>(x);
    reduce_kernel<<<(NCAND + 255) / 256, 256>>>(ntiles);
    select_kernel<<<1, 1>>>((float*)d_out);
}

// round 3
// speedup vs baseline: 1.0221x; 1.0036x over previous
#include <cuda_runtime.h>
#include <stdint.h>

#define NCAND 1600
#define NITER 100
#define NZ    16
#define TILE  4096
#define CBLK  320
#define KPT   5          // CBLK * KPT == NCAND
#define MAXTILES 1024

typedef unsigned long long u64;

// ---------------- device scratch (no allocations allowed) ----------------
__device__ unsigned g_min_enc;
__device__ unsigned g_max_enc;
__device__ u64      g_invs2[NCAND];    // packed (inv_s, inv_s)
__device__ u64      g_negs2[NCAND];    // packed (-s, -s)
__device__ float    g_lo[NCAND];       // -zp
__device__ float    g_hi[NCAND];       // 15 - zp
__device__ float    g_newmin[NCAND];
__device__ float    g_newmax[NCAND];
__device__ float    g_partial[MAXTILES * NCAND];
__device__ double   g_score[NCAND];

// monotonic float<->uint encoding so unsigned atomicMin/Max order floats
__device__ __forceinline__ unsigned enc_f(float f) {
    unsigned u = __float_as_uint(f);
    return (u & 0x80000000u) ? ~u : (u | 0x80000000u);
}
__device__ __forceinline__ float dec_f(unsigned e) {
    return (e & 0x80000000u) ? __uint_as_float(e & 0x7fffffffu)
                             : __uint_as_float(~e);
}

__device__ __forceinline__ u64 pack2(float a, float b) {
    u64 r;
    asm("mov.b64 %0, {%1, %2};" : "=l"(r) : "f"(a), "f"(b));
    return r;
}

__global__ void init_kernel() {
    g_min_enc = 0xFFFFFFFFu;
    g_max_enc = 0u;
}

// ---------------- pass A: global min/max ----------------
__global__ void minmax_kernel(const float4* __restrict__ x4, int n4) {
    float lmin = 3.4e38f, lmax = -3.4e38f;
    for (int i = blockIdx.x * blockDim.x + threadIdx.x; i < n4;
         i += gridDim.x * blockDim.x) {
        float4 v = x4[i];
        lmin = fminf(lmin, fminf(fminf(v.x, v.y), fminf(v.z, v.w)));
        lmax = fmaxf(lmax, fmaxf(fmaxf(v.x, v.y), fmaxf(v.z, v.w)));
    }
    #pragma unroll
    for (int o = 16; o; o >>= 1) {
        lmin = fminf(lmin, __shfl_xor_sync(0xffffffffu, lmin, o));
        lmax = fmaxf(lmax, __shfl_xor_sync(0xffffffffu, lmax, o));
    }
    __shared__ float smin[8], smax[8];
    int w = threadIdx.x >> 5;
    if ((threadIdx.x & 31) == 0) { smin[w] = lmin; smax[w] = lmax; }
    __syncthreads();
    if (threadIdx.x == 0) {
        int nw = blockDim.x >> 5;
        for (int i = 1; i < nw; i++) {
            lmin = fminf(lmin, smin[i]);
            lmax = fmaxf(lmax, smax[i]);
        }
        atomicMin(&g_min_enc, enc_f(lmin));
        atomicMax(&g_max_enc, enc_f(lmax));
    }
}

// ---------------- pass B: 1600 candidate params ----------------
__global__ void cand_kernel() {
    const float x_min = dec_f(g_min_enc);
    const float x_max = dec_f(g_max_enc);
    const float xrange = x_max - x_min;
    const float EPS = 1.1920929e-7f;  // np.finfo(float32).eps
    for (int c = threadIdx.x; c < NCAND; c += blockDim.x) {
        int i = c / NZ + 1;   // 1..100
        int z = c % NZ;       // 0..15
        float fi = (float)i, fz = (float)z;
        float tmp_max   = xrange / 100.0f * fi;
        float tmp_delta = tmp_max / 15.0f;
        float new_min = fmaxf(-fz * tmp_delta, x_min);
        float new_max = fminf(tmp_max - fz * tmp_delta, x_max);
        float min_neg = fminf(new_min, 0.0f);
        float max_pos = fmaxf(new_max, 0.0f);
        float scale = fmaxf((max_pos - min_neg) / 15.0f, EPS);
        // jnp.round == rint (half-to-even)
        float zp = fminf(fmaxf(0.0f - rintf(min_neg / scale), 0.0f), 15.0f);
        float inv_s = 1.0f / scale;
        g_invs2[c] = pack2(inv_s, inv_s);
        g_negs2[c] = pack2(-scale, -scale);
        g_lo[c] = -zp;
        g_hi[c] = 15.0f - zp;
        g_newmin[c] = new_min;
        g_newmax[c] = new_max;
    }
}

// one packed quantize-MSE eval of 2 elements:
//   4 f32x2 fma-pipe ops + 4 scalar FMNMX (alu pipe)
// MAGIC = 12582912.0f (1.5*2^23): fma(x,inv,MAGIC)-MAGIC == rint(x*inv)
// for |x*inv| < 2^22 (guaranteed: |x*inv| <= ~1500 here).
__device__ __forceinline__ void eval2(u64 x2, u64 invs2, u64 negs2,
                                      float lo, float hi, u64& acc2) {
    const u64 MAGIC2    = 0x4B4000004B400000ull;  // (12582912, 12582912)
    const u64 NEGMAGIC2 = 0xCB400000CB400000ull;
    asm("{\n\t"
        ".reg .b64 t2, r2, q2, d2;\n\t"
        ".reg .f32 r0, r1;\n\t"
        "fma.rn.f32x2 t2, %1, %2, %5;\n\t"   // t = x*inv_s + MAGIC
        "add.rn.f32x2 r2, t2, %6;\n\t"       // r = t - MAGIC = rint(x*inv_s)
        "mov.b64 {r0, r1}, r2;\n\t"
        "max.f32 r0, r0, %3;\n\t"
        "min.f32 r0, r0, %4;\n\t"
        "max.f32 r1, r1, %3;\n\t"
        "min.f32 r1, r1, %4;\n\t"
        "mov.b64 q2, {r0, r1};\n\t"
        "fma.rn.f32x2 d2, q2, %7, %1;\n\t"   // d = x - q*s  (exact neg of q*s-x)
        "fma.rn.f32x2 %0, d2, d2, %0;\n\t"   // acc += d*d
        "}"
        : "+l"(acc2)
        : "l"(x2), "l"(invs2), "f"(lo), "f"(hi),
          "l"(MAGIC2), "l"(NEGMAGIC2), "l"(negs2));
}

// ---------------- pass C: the 6.7G-eval score kernel ----------------
__global__ void __launch_bounds__(CBLK) score_kernel(const float* __restrict__ x) {
    __shared__ float sh[TILE];
    const int b = blockIdx.x;
    const float* xp = x + (size_t)b * TILE;
    for (int i = threadIdx.x; i < TILE; i += CBLK) sh[i] = xp[i];

    u64 invs[KPT], negs[KPT], acc[KPT];
    float lo[KPT], hi[KPT];
    #pragma unroll
    for (int k = 0; k < KPT; k++) {
        int c = threadIdx.x + k * CBLK;
        invs[k] = g_invs2[c];
        negs[k] = g_negs2[c];
        lo[k]   = g_lo[c];
        hi[k]   = g_hi[c];
        acc[k]  = 0ull;      // packed (0.0f, 0.0f)
    }
    __syncthreads();

    const ulonglong2* s2 = (const ulonglong2*)sh;   // 2 packed pairs per 128b
    #pragma unroll 2
    for (int e = 0; e < TILE / 4; e++) {
        ulonglong2 xv = s2[e];   // broadcast LDS.128 (all lanes same addr)
        #pragma unroll
        for (int k = 0; k < KPT; k++) {
            eval2(xv.x, invs[k], negs[k], lo[k], hi[k], acc[k]);
            eval2(xv.y, invs[k], negs[k], lo[k], hi[k], acc[k]);
        }
    }

    #pragma unroll
    for (int k = 0; k < KPT; k++) {
        float a0, a1;
        asm("mov.b64 {%0, %1}, %2;" : "=f"(a0), "=f"(a1) : "l"(acc[k]));
        g_partial[b * NCAND + threadIdx.x + k * CBLK] = a0 + a1;
    }
}

// ---------------- pass D: deterministic fixed-order reduction ----------------
__global__ void reduce_kernel(int ntiles) {
    int c = blockIdx.x * blockDim.x + threadIdx.x;
    if (c >= NCAND) return;
    double s = 0.0;
    for (int b = 0; b < ntiles; b++)
        s += (double)g_partial[b * NCAND + c];
    g_score[c] = s;
}

// ---------------- pass E: replicate the reference scan exactly ----------------
__global__ void select_kernel(float* __restrict__ out) {
    double best = 1e30;
    float bmin = dec_f(g_min_enc);
    float bmax = dec_f(g_max_enc);
    for (int i = 0; i < NITER; i++) {
        int j = 0;
        double sm = g_score[i * NZ];
        for (int z = 1; z < NZ; z++) {        // first-occurrence argmin
            double s = g_score[i * NZ + z];
            if (s < sm) { sm = s; j = z; }
        }
        if (sm < best) {                       // strict <, like reference
            best = sm;
            bmin = g_newmin[i * NZ + j];
            bmax = g_newmax[i * NZ + j];
        }
    }
    out[0] = bmin;
    out[1] = bmax;
}

extern "C" void kernel_launch(void* const* d_in, const int* in_sizes, int n_in,
                              void* d_out, int out_size) {
    const float* x = (const float*)d_in[0];
    int n = in_sizes[0];
    int ntiles = n / TILE;           // 1024 for 1024x4096
    if (ntiles > MAXTILES) ntiles = MAXTILES;

    init_kernel<<<1, 1>>>();
    minmax_kernel<<<512, 256>>>((const float4*)x, n / 4);
    cand_kernel<<<1, 256>>>();
    score_kernel<<<ntiles, CBLK>>>(x);
    reduce_kernel<<<(NCAND + 255) / 256, 256>>>(ntiles);
    select_kernel<<<1, 1>>>((float*)d_out);
}

// round 4
// speedup vs baseline: 12.9863x; 12.7049x over previous
#include <cuda_runtime.h>
#include <stdint.h>

#define NCAND  1600
#define NITER  100
#define NZ     16
#define NB     524288
#define CHUNK  1024
#define NCHUNK (NB / CHUNK)
#define MMGRID 512

typedef unsigned long long u64;
typedef unsigned u32;

#define FIXS    68719476736.0   // 2^36
#define INVFIXS (1.0 / 68719476736.0)

__device__ u32    g_min_enc;
__device__ u32    g_max_enc;
__device__ float  g_xminf;
__device__ float  g_invwf;
__device__ double g_S2tot;
__device__ double g_s2blk[MMGRID];
__device__ float  g_sc[NCAND];
__device__ float  g_ql[NCAND];
__device__ float  g_newmin[NCAND];
__device__ float  g_newmax[NCAND];
__device__ double g_score[NCAND];
__device__ u32    g_cnt[NB];
__device__ u64    g_sum[NB];
__device__ u32    g_pc[NB + 1];
__device__ u64    g_ps[NB + 1];
__device__ u32    g_ccnt[NCHUNK];
__device__ u64    g_csum[NCHUNK];

__device__ __forceinline__ u32 enc_f(float f) {
    u32 u = __float_as_uint(f);
    return (u & 0x80000000u) ? ~u : (u | 0x80000000u);
}
__device__ __forceinline__ float dec_f(u32 e) {
    return (e & 0x80000000u) ? __uint_as_float(e & 0x7fffffffu)
                             : __uint_as_float(~e);
}

__global__ void clear_kernel() {
    int i = blockIdx.x * blockDim.x + threadIdx.x;
    if (i < NB) { g_cnt[i] = 0u; g_sum[i] = 0ull; }
    if (i == 0) { g_min_enc = 0xFFFFFFFFu; g_max_enc = 0u; }
}

__global__ void minmax_s2_kernel(const float4* __restrict__ x4, int n4) {
    float lmin = 3.4e38f, lmax = -3.4e38f;
    double s2 = 0.0;
    for (int i = blockIdx.x * blockDim.x + threadIdx.x; i < n4;
         i += gridDim.x * blockDim.x) {
        float4 v = x4[i];
        lmin = fminf(lmin, fminf(fminf(v.x, v.y), fminf(v.z, v.w)));
        lmax = fmaxf(lmax, fmaxf(fmaxf(v.x, v.y), fmaxf(v.z, v.w)));
        s2 += (double)v.x * v.x + (double)v.y * v.y
            + (double)v.z * v.z + (double)v.w * v.w;
    }
    #pragma unroll
    for (int o = 16; o; o >>= 1) {
        lmin = fminf(lmin, __shfl_xor_sync(0xffffffffu, lmin, o));
        lmax = fmaxf(lmax, __shfl_xor_sync(0xffffffffu, lmax, o));
        s2  += __shfl_xor_sync(0xffffffffu, s2, o);
    }
    __shared__ float  smin[8], smax[8];
    __shared__ double ss2[8];
    int w = threadIdx.x >> 5;
    if ((threadIdx.x & 31) == 0) { smin[w] = lmin; smax[w] = lmax; ss2[w] = s2; }
    __syncthreads();
    if (threadIdx.x == 0) {
        double b2 = 0.0;
        for (int i = 0; i < (int)(blockDim.x >> 5); i++) {
            lmin = fminf(lmin, smin[i]);
            lmax = fmaxf(lmax, smax[i]);
            b2 += ss2[i];
        }
        atomicMin(&g_min_enc, enc_f(lmin));
        atomicMax(&g_max_enc, enc_f(lmax));
        g_s2blk[blockIdx.x] = b2;
    }
}

__global__ void __launch_bounds__(512) cand_kernel() {
    __shared__ double sd[512];
    int t = threadIdx.x;
    sd[t] = g_s2blk[t];           // MMGRID == 512
    __syncthreads();
    for (int off = 256; off; off >>= 1) {
        if (t < off) sd[t] += sd[t + off];
        __syncthreads();
    }
    const float x_min = dec_f(g_min_enc);
    const float x_max = dec_f(g_max_enc);
    const float xrange = x_max - x_min;
    if (t == 0) {
        g_S2tot = sd[0];
        g_xminf = x_min;
        g_invwf = (float)NB / xrange;
    }
    const float EPS = 1.1920929e-7f;
    for (int c = t; c < NCAND; c += 512) {
        int i = c / NZ + 1;
        int z = c % NZ;
        float fi = (float)i, fz = (float)z;
        float tmp_max   = xrange / 100.0f * fi;
        float tmp_delta = tmp_max / 15.0f;
        float new_min = fmaxf(-fz * tmp_delta, x_min);
        float new_max = fminf(tmp_max - fz * tmp_delta, x_max);
        float min_neg = fminf(new_min, 0.0f);
        float max_pos = fmaxf(new_max, 0.0f);
        float scale = fmaxf((max_pos - min_neg) / 15.0f, EPS);
        float zp = fminf(fmaxf(0.0f - rintf(min_neg / scale), 0.0f), 15.0f);
        g_sc[c] = scale;
        g_ql[c] = -zp;
        g_newmin[c] = new_min;
        g_newmax[c] = new_max;
    }
}

__global__ void hist_kernel(const float4* __restrict__ x4, int n4) {
    const float xminf = g_xminf;
    const float invwf = g_invwf;
    for (int i = blockIdx.x * blockDim.x + threadIdx.x; i < n4;
         i += gridDim.x * blockDim.x) {
        float4 v = x4[i];
        float f[4] = {v.x, v.y, v.z, v.w};
        #pragma unroll
        for (int k = 0; k < 4; k++) {
            float d = f[k] - xminf;
            int b = (int)(d * invwf);
            b = min(max(b, 0), NB - 1);
            double dd = (double)f[k] - (double)xminf;   // exact
            u64 fx = (u64)(long long)llrint(dd * FIXS);
            atomicAdd(&g_cnt[b], 1u);
            atomicAdd(&g_sum[b], fx);
        }
    }
}

__global__ void chunkred_kernel() {
    __shared__ u32 sc[256];
    __shared__ u64 ss[256];
    int b = blockIdx.x, t = threadIdx.x;
    u32 c = 0; u64 s = 0;
    for (int j = t; j < CHUNK; j += 256) {
        c += g_cnt[b * CHUNK + j];
        s += g_sum[b * CHUNK + j];
    }
    sc[t] = c; ss[t] = s; __syncthreads();
    for (int off = 128; off; off >>= 1) {
        if (t < off) { sc[t] += sc[t + off]; ss[t] += ss[t + off]; }
        __syncthreads();
    }
    if (t == 0) { g_ccnt[b] = sc[0]; g_csum[b] = ss[0]; }
}

__global__ void __launch_bounds__(NCHUNK) chunkscan_kernel() {
    __shared__ u32 sc[NCHUNK];
    __shared__ u64 ss[NCHUNK];
    int t = threadIdx.x;
    u32 v = g_ccnt[t];
    u64 w = g_csum[t];
    sc[t] = v; ss[t] = w; __syncthreads();
    for (int off = 1; off < NCHUNK; off <<= 1) {
        u32 a = 0; u64 a2 = 0;
        if (t >= off) { a = sc[t - off]; a2 = ss[t - off]; }
        __syncthreads();
        sc[t] += a; ss[t] += a2;
        __syncthreads();
    }
    g_ccnt[t] = sc[t] - v;   // exclusive
    g_csum[t] = ss[t] - w;
}

__global__ void __launch_bounds__(CHUNK) binscan_kernel() {
    __shared__ u32 sc[CHUNK];
    __shared__ u64 ss[CHUNK];
    int b = blockIdx.x, t = threadIdx.x;
    int i = b * CHUNK + t;
    u32 v = g_cnt[i];
    u64 w = g_sum[i];
    sc[t] = v; ss[t] = w; __syncthreads();
    for (int off = 1; off < CHUNK; off <<= 1) {
        u32 a = 0; u64 a2 = 0;
        if (t >= off) { a = sc[t - off]; a2 = ss[t - off]; }
        __syncthreads();
        sc[t] += a; ss[t] += a2;
        __syncthreads();
    }
    g_pc[i] = g_ccnt[b] + (sc[t] - v);
    g_ps[i] = g_csum[b] + (ss[t] - w);
    if (i == NB - 1) {
        g_pc[NB] = g_ccnt[b] + sc[t];
        g_ps[NB] = g_csum[b] + ss[t];
    }
}

__device__ __forceinline__ int gidx(float E, float xminf, float invwf) {
    float t = (E - xminf) * invwf;
    if (!(t > 0.0f)) return 0;
    if (t >= (float)NB) return NB;
    return (int)t;
}

__global__ void assemble_kernel(int ntot) {
    int c = blockIdx.x * blockDim.x + threadIdx.x;
    if (c >= NCAND) return;
    const float xminf = g_xminf;
    const float invwf = g_invwf;
    const double xmind = (double)xminf;
    float s  = g_sc[c];
    float ql = g_ql[c];
    int e[NZ + 1];
    e[0] = 0; e[NZ] = NB;
    #pragma unroll
    for (int m = 0; m < NZ - 1; m++)
        e[m + 1] = gidx((ql + (float)m + 0.5f) * s, xminf, invwf);
    #pragma unroll
    for (int m = 1; m < NZ; m++) if (e[m] < e[m - 1]) e[m] = e[m - 1];
    double num = 0.0;
    #pragma unroll
    for (int m = 0; m < NZ; m++) {
        u32 pc0 = g_pc[e[m]],  pc1 = g_pc[e[m + 1]];
        u64 ps0 = g_ps[e[m]],  ps1 = g_ps[e[m + 1]];
        double Nm = (double)(pc1 - pc0);
        double S1 = (double)(long long)(ps1 - ps0) * INVFIXS + Nm * xmind;
        float a = (ql + (float)m) * s;
        double ad = (double)a;
        num += ad * ad * Nm - 2.0 * ad * S1;
    }
    g_score[c] = (num + g_S2tot) / (double)ntot;
}

__global__ void __launch_bounds__(128) select_kernel(float* __restrict__ out) {
    __shared__ double sm_i[NITER];
    __shared__ int    j_i[NITER];
    int t = threadIdx.x;
    if (t < NITER) {
        int j = 0;
        double sm = g_score[t * NZ];
        #pragma unroll
        for (int z = 1; z < NZ; z++) {
            double s = g_score[t * NZ + z];
            if (s < sm) { sm = s; j = z; }
        }
        sm_i[t] = sm; j_i[t] = j;
    }
    __syncthreads();
    if (t == 0) {
        double best = 1e30;
        float bmin = dec_f(g_min_enc);
        float bmax = dec_f(g_max_enc);
        for (int i = 0; i < NITER; i++) {
            if (sm_i[i] < best) {
                best = sm_i[i];
                bmin = g_newmin[i * NZ + j_i[i]];
                bmax = g_newmax[i * NZ + j_i[i]];
            }
        }
        out[0] = bmin;
        out[1] = bmax;
    }
}

extern "C" void kernel_launch(void* const* d_in, const int* in_sizes, int n_in,
                              void* d_out, int out_size) {
    const float* x = (const float*)d_in[0];
    int n = in_sizes[0];
    int n4 = n / 4;

    clear_kernel<<<NB / 1024, 1024>>>();
    minmax_s2_kernel<<<MMGRID, 256>>>((const float4*)x, n4);
    cand_kernel<<<1, 512>>>();
    hist_kernel<<<2048, 256>>>((const float4*)x, n4);
    chunkred_kernel<<<NCHUNK, 256>>>();
    chunkscan_kernel<<<1, NCHUNK>>>();
    binscan_kernel<<<NCHUNK, CHUNK>>>();
    assemble_kernel<<<(NCAND + 127) / 128, 128>>>(n);
    select_kernel<<<1, 128>>>((float*)d_out);
}